// round 1
// baseline (speedup 1.0000x reference)
#include <cuda_runtime.h>
#include <cuda_bf16.h>
#include <math.h>

// Problem constants
#define BB 256
#define TT 16
#define SS 20
#define DD 256
#define NN (BB*TT)          // 4096
#define TD (3*DD)           // 768
#define NC 1536             // 2*TD columns of precompute GEMM

// ---------------- device scratch (no cudaMalloc allowed) ----------------
__device__ float g_Bt[DD * NC];            // [k][j] rearranged W_ih  (1.5 MB)
__device__ float g_Wt[DD * TD];            // [k][j] W_hh transposed  (0.75 MB)
__device__ float g_G[(size_t)SS * NN * NC];// [s][n][1536]  (503 MB)
__device__ float g_h[NN * DD];             // hidden state
__device__ float g_m[NN];                  // soft readout multiplier
__device__ float g_gh[NN * TD];            // per-step h @ W_hh^T

// ---------------- prep: weight rearrangement ----------------
__global__ void prep_weights(const float* __restrict__ W_ih,
                             const float* __restrict__ W_hh) {
    int idx = blockIdx.x * blockDim.x + threadIdx.x;
    int stride = gridDim.x * blockDim.x;
    // Bt[k*1536 + j]: j<768 -> W_ih[j][k], else W_ih[j-768][256+k]
    for (int i = idx; i < DD * NC; i += stride) {
        int k = i / NC, j = i % NC;
        float v;
        if (j < TD) v = W_ih[(size_t)j * (2*DD) + k];
        else        v = W_ih[(size_t)(j - TD) * (2*DD) + DD + k];
        g_Bt[i] = v;
    }
    // Wt[k*768 + j] = W_hh[j][k]
    for (int i = idx; i < DD * TD; i += stride) {
        int k = i / TD, j = i % TD;
        g_Wt[i] = W_hh[(size_t)j * DD + k];
    }
}

// ---------------- init h, m ----------------
__global__ void init_hm(const int* __restrict__ user_idxs,
                        const float* __restrict__ user_table) {
    int n = blockIdx.x;
    int d = threadIdx.x;
    g_h[n * DD + d] = user_table[(size_t)user_idxs[n] * DD + d];
    if (d == 0) g_m[n] = 1.0f;
}

// ---------------- classic 128x128x8 fp32 GEMM, optional gather of A rows ----
// C[M x Ncols] = A[M x K] * Bt  where Bt is stored [k][Ncols] row-major.
// GATHER: A row r -> item_table[item_idxs[n*20+s]] with r = s*4096 + n.
template<bool GATHER>
__global__ __launch_bounds__(256)
void gemm128(const float* __restrict__ A,
             const float* __restrict__ Bt,
             float* __restrict__ C,
             int Ncols, int K,
             const int* __restrict__ item_idxs,
             const float* __restrict__ table) {
    __shared__ float As[8][128];
    __shared__ float Bs[8][128];
    __shared__ const float* rowPtr[128];

    const int bx = blockIdx.x;   // col tile
    const int by = blockIdx.y;   // row tile
    const int tid = threadIdx.x;

    if (tid < 128) {
        int r = by * 128 + tid;
        if (GATHER) {
            int s = r >> 12;          // / 4096
            int n = r & 4095;
            rowPtr[tid] = table + (size_t)item_idxs[n * SS + s] * DD;
        } else {
            rowPtr[tid] = A + (size_t)r * K;
        }
    }
    __syncthreads();

    const int tx = tid & 15;     // 0..15
    const int ty = tid >> 4;     // 0..15

    const int aRow  = tid >> 1;        // 0..127
    const int aCol4 = (tid & 1) * 4;   // 0 or 4
    const int bRow  = tid >> 5;        // 0..7
    const int bCol4 = (tid & 31) * 4;  // 0..124

    const float* BtBase = Bt + bx * 128;

    float acc[8][8];
#pragma unroll
    for (int i = 0; i < 8; i++)
#pragma unroll
        for (int j = 0; j < 8; j++) acc[i][j] = 0.0f;

    for (int kk = 0; kk < K; kk += 8) {
        float4 av = *(const float4*)(rowPtr[aRow] + kk + aCol4);
        As[aCol4 + 0][aRow] = av.x;
        As[aCol4 + 1][aRow] = av.y;
        As[aCol4 + 2][aRow] = av.z;
        As[aCol4 + 3][aRow] = av.w;
        float4 bv = *(const float4*)(BtBase + (size_t)(kk + bRow) * Ncols + bCol4);
        *(float4*)&Bs[bRow][bCol4] = bv;
        __syncthreads();

#pragma unroll
        for (int k = 0; k < 8; k++) {
            float ra[8], rb[8];
#pragma unroll
            for (int i = 0; i < 8; i++) ra[i] = As[k][ty * 8 + i];
#pragma unroll
            for (int j = 0; j < 8; j++) rb[j] = Bs[k][tx * 8 + j];
#pragma unroll
            for (int i = 0; i < 8; i++)
#pragma unroll
                for (int j = 0; j < 8; j++)
                    acc[i][j] = fmaf(ra[i], rb[j], acc[i][j]);
        }
        __syncthreads();
    }

#pragma unroll
    for (int i = 0; i < 8; i++) {
        int row = by * 128 + ty * 8 + i;
        float* cp = C + (size_t)row * Ncols + bx * 128 + tx * 8;
        float4 v0 = make_float4(acc[i][0], acc[i][1], acc[i][2], acc[i][3]);
        float4 v1 = make_float4(acc[i][4], acc[i][5], acc[i][6], acc[i][7]);
        *(float4*)(cp + 0) = v0;
        *(float4*)(cp + 4) = v1;
    }
}

// ---------------- fused GRU gate math + y reduction + state update ----------
__device__ __forceinline__ float sigmoidf_(float x) {
    return 1.0f / (1.0f + expf(-x));
}

__global__ __launch_bounds__(256)
void gru_step(const float* __restrict__ b_ih,
              const float* __restrict__ b_hh,
              const float* __restrict__ W_out,
              const float* __restrict__ b_out,
              float* __restrict__ out,
              int s) {
    const int n = blockIdx.x;   // 0..4095
    const int d = threadIdx.x;  // 0..255

    const float* Grow  = g_G + ((size_t)s * NN + n) * NC;
    const float* ghrow = g_gh + (size_t)n * TD;

    float mm = g_m[n];
    float hv = g_h[n * DD + d];

    float gir = Grow[d]        + mm * Grow[TD + d]        + b_ih[d];
    float giz = Grow[DD + d]   + mm * Grow[TD + DD + d]   + b_ih[DD + d];
    float gin = Grow[2*DD + d] + mm * Grow[TD + 2*DD + d] + b_ih[2*DD + d];

    float ghr = ghrow[d]        + b_hh[d];
    float ghz = ghrow[DD + d]   + b_hh[DD + d];
    float ghn = ghrow[2*DD + d] + b_hh[2*DD + d];

    float r  = sigmoidf_(gir + ghr);
    float z  = sigmoidf_(giz + ghz);
    float nn = tanhf(gin + r * ghn);
    float hn = (1.0f - z) * nn + z * hv;

    g_h[n * DD + d] = hn;

    // y = hn . W_out + b_out  (block reduction over 256 lanes)
    float part = hn * W_out[d];
#pragma unroll
    for (int off = 16; off > 0; off >>= 1)
        part += __shfl_down_sync(0xFFFFFFFFu, part, off);

    __shared__ float warpsum[8];
    if ((d & 31) == 0) warpsum[d >> 5] = part;
    __syncthreads();
    if (d == 0) {
        float y = b_out[0];
#pragma unroll
        for (int w = 0; w < 8; w++) y += warpsum[w];
        out[n * SS + s] = y;
        g_m[n] = sigmoidf_(y);
    }
}

// ---------------- launch ----------------
extern "C" void kernel_launch(void* const* d_in, const int* in_sizes, int n_in,
                              void* d_out, int out_size) {
    const int*   item_idxs  = (const int*)  d_in[0];
    const int*   user_idxs  = (const int*)  d_in[1];
    // d_in[2] = responses (unused)
    const float* item_table = (const float*)d_in[3];
    const float* user_table = (const float*)d_in[4];
    const float* W_ih       = (const float*)d_in[5];
    const float* W_hh       = (const float*)d_in[6];
    const float* b_ih       = (const float*)d_in[7];
    const float* b_hh       = (const float*)d_in[8];
    const float* W_out      = (const float*)d_in[9];
    const float* b_out      = (const float*)d_in[10];
    float* out = (float*)d_out;

    float *Bt_p, *Wt_p, *G_p, *h_p, *gh_p;
    cudaGetSymbolAddress((void**)&Bt_p, g_Bt);
    cudaGetSymbolAddress((void**)&Wt_p, g_Wt);
    cudaGetSymbolAddress((void**)&G_p,  g_G);
    cudaGetSymbolAddress((void**)&h_p,  g_h);
    cudaGetSymbolAddress((void**)&gh_p, g_gh);

    // 1) rearrange weights
    prep_weights<<<148, 256>>>(W_ih, W_hh);

    // 2) init h, m
    init_hm<<<NN, DD>>>(user_idxs, user_table);

    // 3) precompute G = gather(E) @ Bt   (M=81920, Ncols=1536, K=256)
    {
        dim3 grid(NC / 128, (SS * NN) / 128);   // 12 x 640
        gemm128<true><<<grid, 256>>>(nullptr, Bt_p, G_p, NC, DD,
                                     item_idxs, item_table);
    }

    // 4) 20 sequential GRU steps
    for (int s = 0; s < SS; s++) {
        dim3 grid(TD / 128, NN / 128);          // 6 x 32
        gemm128<false><<<grid, 256>>>(h_p, Wt_p, gh_p, TD, DD,
                                      nullptr, nullptr);
        gru_step<<<NN, DD>>>(b_ih, b_hh, W_out, b_out, out, s);
    }
}

// round 10
// speedup vs baseline: 1.2092x; 1.2092x over previous
#include <cuda_runtime.h>
#include <math.h>
#include <cstdint>

// Problem constants
#define BB 256
#define TT 16
#define SS 20
#define DD 256
#define NN (BB*TT)          // 4096
#define TD (3*DD)           // 768
#define NC 1536             // 2*TD columns of precompute GEMM

// ---------------- device scratch ----------------
__device__ float g_G[(size_t)SS * NN * NC];// [s][n][1536]  (503 MB)
__device__ float g_h[NN * DD];             // hidden state
__device__ float g_m[NN];                  // soft readout multiplier
__device__ float g_gh[NN * TD];            // per-step h @ W_hh^T

// ---------------- helpers ----------------
__device__ __forceinline__ uint32_t smem_u32(const void* p) {
    uint32_t a;
    asm("{ .reg .u64 t; cvta.to.shared.u64 t, %1; cvt.u32.u64 %0, t; }"
        : "=r"(a) : "l"(p));
    return a;
}
__device__ __forceinline__ void cp16(uint32_t dst, const void* src) {
    asm volatile("cp.async.cg.shared.global [%0], [%1], 16;"
                 :: "r"(dst), "l"(src) : "memory");
}
__device__ __forceinline__ void cp_commit() {
    asm volatile("cp.async.commit_group;" ::: "memory");
}
template<int N>
__device__ __forceinline__ void cp_wait() {
    asm volatile("cp.async.wait_group %0;" :: "n"(N) : "memory");
}
__device__ __forceinline__ uint32_t f2tf32(float v) {
    uint32_t o;
    asm("cvt.rna.tf32.f32 %0, %1;" : "=r"(o) : "f"(v));
    return o;
}
__device__ __forceinline__ void mma_tf32(float c[4],
                                         uint32_t a0, uint32_t a1, uint32_t a2, uint32_t a3,
                                         uint32_t b0, uint32_t b1) {
    asm volatile(
        "mma.sync.aligned.m16n8k8.row.col.f32.tf32.tf32.f32 "
        "{%0,%1,%2,%3}, {%4,%5,%6,%7}, {%8,%9}, {%0,%1,%2,%3};"
        : "+f"(c[0]), "+f"(c[1]), "+f"(c[2]), "+f"(c[3])
        : "r"(a0), "r"(a1), "r"(a2), "r"(a3), "r"(b0), "r"(b1));
}

// ---------------- smem layout (dynamic, bytes) ----------------
// rpA: 128 ptrs (1024B) | rpB: 128 ptrs (1024B)
// stage s (s=0,1): A[128][36] f32 (18432B) + B[128][36] f32 (18432B)
#define SM_RPA   0
#define SM_RPB   1024
#define SM_TILES 2048
#define TILE_STRIDE 36              // floats per row (bank-conflict pad)
#define TILE_BYTES  (128*TILE_STRIDE*4)   // 18432
#define STAGE_BYTES (2*TILE_BYTES)        // 36864
#define SM_TOTAL (SM_TILES + 2*STAGE_BYTES)  // 75776

// ======== 3xTF32 mma.sync GEMM: C[Mtot x Ncols] = A[Mtot x 256] @ Brows^T ====
// CTA tile 128(M) x 128(N), K=256 in 8 chunks of 32, cp.async double buffered.
// 8 warps: warpM = wid&1 (tile 64), warpN = wid>>1 (tile 32).
// Fragment mapping per PTX ISA (m16n8k8.tf32):
//   a0=(g,tg) a1=(g+8,tg) a2=(g,tg+4) a3=(g+8,tg+4)
//   b0=(k=tg,n=g) b1=(k=tg+4,n=g)   (B stored [n][k] in smem)
//   c0,c1=(g, 2tg,2tg+1)  c2,c3=(g+8, 2tg,2tg+1)
// AMODE 1: A row r -> item_table[item_idxs[n*20+s]], r = s*4096+n.
// BMODE 1: B row j -> merged W_ih: row (j<768 ? j : j-768), +256 col if j>=768.
template<int AMODE, int BMODE>
__global__ __launch_bounds__(256)
void gemm_tc(const float* __restrict__ Aplain,
             const float* __restrict__ Bsrc,
             float* __restrict__ C,
             int Ncols,
             const int* __restrict__ item_idxs,
             const float* __restrict__ item_table) {
    extern __shared__ char smem[];
    const uint32_t smem_base = smem_u32(smem);
    const int tid  = threadIdx.x;
    const int wid  = tid >> 5;
    const int lane = tid & 31;
    const int bx = blockIdx.x, by = blockIdx.y;

    const float** rpA = (const float**)(smem + SM_RPA);
    const float** rpB = (const float**)(smem + SM_RPB);

    if (tid < 128) {
        int r = by * 128 + tid;
        const float* p;
        if (AMODE == 1) {
            int s = r >> 12, n = r & 4095;
            p = item_table + (size_t)item_idxs[n * SS + s] * DD;
        } else {
            p = Aplain + (size_t)r * DD;
        }
        rpA[tid] = p;
    } else {
        int j = bx * 128 + (tid - 128);
        const float* q;
        if (BMODE == 1) {
            int jj = (j >= TD) ? (j - TD) : j;       // FIX: true mod-768 (j&767 was wrong)
            q = Bsrc + (size_t)jj * (2 * DD) + (j >= TD ? DD : 0);
        } else {
            q = Bsrc + (size_t)j * DD;
        }
        rpB[tid - 128] = q;
    }
    __syncthreads();

    // per-thread copy role: 2 threads per row, 16 floats each
    const int crow  = tid & 127;
    const int chalf = tid >> 7;                // 0 or 1 (k-half of 32)
    const float* aSrcBase = rpA[crow] + chalf * 16;
    const float* bSrcBase = rpB[crow] + chalf * 16;
    const uint32_t aDstBase = smem_base + SM_TILES + (uint32_t)crow * (TILE_STRIDE*4) + chalf * 64;
    const uint32_t bDstBase = aDstBase + TILE_BYTES;

    auto prefetch = [&](int kc, int buf) {
        uint32_t so = (uint32_t)buf * STAGE_BYTES;
        const float* as = aSrcBase + kc * 32;
        const float* bs = bSrcBase + kc * 32;
#pragma unroll
        for (int q = 0; q < 4; q++) {
            cp16(aDstBase + so + q * 16, as + q * 4);
            cp16(bDstBase + so + q * 16, bs + q * 4);
        }
    };

    const int warpM = wid & 1;
    const int warpN = wid >> 1;
    const int g  = lane >> 2;
    const int tg = lane & 3;
    const int mb = warpM * 64;
    const int nb = warpN * 32;

    float c[4][4][4];
#pragma unroll
    for (int mt = 0; mt < 4; mt++)
#pragma unroll
        for (int nt = 0; nt < 4; nt++)
#pragma unroll
            for (int e = 0; e < 4; e++) c[mt][nt][e] = 0.0f;

    prefetch(0, 0);
    cp_commit();

    for (int kc = 0; kc < 8; kc++) {
        if (kc < 7) {
            prefetch(kc + 1, (kc + 1) & 1);
            cp_commit();
            cp_wait<1>();
        } else {
            cp_wait<0>();
        }
        __syncthreads();

        const float* As = (const float*)(smem + SM_TILES + (kc & 1) * STAGE_BYTES);
        const float* Bs = As + 128 * TILE_STRIDE;

#pragma unroll
        for (int ks = 0; ks < 4; ks++) {
            const int k = ks * 8;
            // B fragments (hi/lo): b0=(k=tg,n), b1=(k=tg+4,n)
            uint32_t bhi[4][2], blo[4][2];
#pragma unroll
            for (int nt = 0; nt < 4; nt++) {
                float b0 = Bs[(nb + nt * 8 + g) * TILE_STRIDE + k + tg];
                float b1 = Bs[(nb + nt * 8 + g) * TILE_STRIDE + k + tg + 4];
                bhi[nt][0] = f2tf32(b0);
                blo[nt][0] = f2tf32(b0 - __uint_as_float(bhi[nt][0]));
                bhi[nt][1] = f2tf32(b1);
                blo[nt][1] = f2tf32(b1 - __uint_as_float(bhi[nt][1]));
            }
#pragma unroll
            for (int mt = 0; mt < 4; mt++) {
                const int r0 = (mb + mt * 16 + g) * TILE_STRIDE;
                const int r1 = (mb + mt * 16 + g + 8) * TILE_STRIDE;
                float a0 = As[r0 + k + tg];        // (g,   tg)
                float a1 = As[r1 + k + tg];        // (g+8, tg)
                float a2 = As[r0 + k + tg + 4];    // (g,   tg+4)
                float a3 = As[r1 + k + tg + 4];    // (g+8, tg+4)
                uint32_t ah0 = f2tf32(a0), ah1 = f2tf32(a1), ah2 = f2tf32(a2), ah3 = f2tf32(a3);
                uint32_t al0 = f2tf32(a0 - __uint_as_float(ah0));
                uint32_t al1 = f2tf32(a1 - __uint_as_float(ah1));
                uint32_t al2 = f2tf32(a2 - __uint_as_float(ah2));
                uint32_t al3 = f2tf32(a3 - __uint_as_float(ah3));
#pragma unroll
                for (int nt = 0; nt < 4; nt++) {
                    mma_tf32(c[mt][nt], al0, al1, al2, al3, bhi[nt][0], bhi[nt][1]);
                    mma_tf32(c[mt][nt], ah0, ah1, ah2, ah3, blo[nt][0], blo[nt][1]);
                    mma_tf32(c[mt][nt], ah0, ah1, ah2, ah3, bhi[nt][0], bhi[nt][1]);
                }
            }
        }
        __syncthreads();
    }

    // epilogue
#pragma unroll
    for (int mt = 0; mt < 4; mt++) {
        int row0 = by * 128 + mb + mt * 16 + g;
        int row1 = row0 + 8;
        float* c0p = C + (size_t)row0 * Ncols + bx * 128 + nb;
        float* c1p = C + (size_t)row1 * Ncols + bx * 128 + nb;
#pragma unroll
        for (int nt = 0; nt < 4; nt++) {
            int col = nt * 8 + tg * 2;
            *(float2*)(c0p + col) = make_float2(c[mt][nt][0], c[mt][nt][1]);
            *(float2*)(c1p + col) = make_float2(c[mt][nt][2], c[mt][nt][3]);
        }
    }
}

// ---------------- init h, m ----------------
__global__ void init_hm(const int* __restrict__ user_idxs,
                        const float* __restrict__ user_table) {
    int n = blockIdx.x;
    int d = threadIdx.x;
    g_h[n * DD + d] = user_table[(size_t)user_idxs[n] * DD + d];
    if (d == 0) g_m[n] = 1.0f;
}

// ---------------- fused GRU gate math + y reduction + state update ----------
__device__ __forceinline__ float sigmoidf_(float x) {
    return 1.0f / (1.0f + expf(-x));
}

__global__ __launch_bounds__(256)
void gru_step(const float* __restrict__ b_ih,
              const float* __restrict__ b_hh,
              const float* __restrict__ W_out,
              const float* __restrict__ b_out,
              float* __restrict__ out,
              int s) {
    const int n = blockIdx.x;
    const int d = threadIdx.x;

    const float* Grow  = g_G + ((size_t)s * NN + n) * NC;
    const float* ghrow = g_gh + (size_t)n * TD;

    float mm = g_m[n];
    float hv = g_h[n * DD + d];

    float gir = Grow[d]        + mm * Grow[TD + d]        + b_ih[d];
    float giz = Grow[DD + d]   + mm * Grow[TD + DD + d]   + b_ih[DD + d];
    float gin = Grow[2*DD + d] + mm * Grow[TD + 2*DD + d] + b_ih[2*DD + d];

    float ghr = ghrow[d]        + b_hh[d];
    float ghz = ghrow[DD + d]   + b_hh[DD + d];
    float ghn = ghrow[2*DD + d] + b_hh[2*DD + d];

    float r  = sigmoidf_(gir + ghr);
    float z  = sigmoidf_(giz + ghz);
    float nn = tanhf(gin + r * ghn);
    float hn = (1.0f - z) * nn + z * hv;

    g_h[n * DD + d] = hn;

    float part = hn * W_out[d];
#pragma unroll
    for (int off = 16; off > 0; off >>= 1)
        part += __shfl_down_sync(0xFFFFFFFFu, part, off);

    __shared__ float warpsum[8];
    if ((d & 31) == 0) warpsum[d >> 5] = part;
    __syncthreads();
    if (d == 0) {
        float y = b_out[0];
#pragma unroll
        for (int w = 0; w < 8; w++) y += warpsum[w];
        out[n * SS + s] = y;
        g_m[n] = sigmoidf_(y);
    }
}

// ---------------- launch ----------------
extern "C" void kernel_launch(void* const* d_in, const int* in_sizes, int n_in,
                              void* d_out, int out_size) {
    const int*   item_idxs  = (const int*)  d_in[0];
    const int*   user_idxs  = (const int*)  d_in[1];
    const float* item_table = (const float*)d_in[3];
    const float* user_table = (const float*)d_in[4];
    const float* W_ih       = (const float*)d_in[5];
    const float* W_hh       = (const float*)d_in[6];
    const float* b_ih       = (const float*)d_in[7];
    const float* b_hh       = (const float*)d_in[8];
    const float* W_out      = (const float*)d_in[9];
    const float* b_out      = (const float*)d_in[10];
    float* out = (float*)d_out;

    float *G_p, *h_p, *gh_p;
    cudaGetSymbolAddress((void**)&G_p,  g_G);
    cudaGetSymbolAddress((void**)&h_p,  g_h);
    cudaGetSymbolAddress((void**)&gh_p, g_gh);

    cudaFuncSetAttribute(gemm_tc<1,1>, cudaFuncAttributeMaxDynamicSharedMemorySize, SM_TOTAL);
    cudaFuncSetAttribute(gemm_tc<0,0>, cudaFuncAttributeMaxDynamicSharedMemorySize, SM_TOTAL);

    // init h, m
    init_hm<<<NN, DD>>>(user_idxs, user_table);

    // precompute G = gather(E) @ [W1 | W2]^T   (M=81920, Ncols=1536, K=256)
    {
        dim3 grid(NC / 128, (SS * NN) / 128);   // 12 x 640
        gemm_tc<1,1><<<grid, 256, SM_TOTAL>>>(nullptr, W_ih, G_p, NC,
                                              item_idxs, item_table);
    }

    // 20 sequential GRU steps
    for (int s = 0; s < SS; s++) {
        dim3 grid(TD / 128, NN / 128);          // 6 x 32
        gemm_tc<0,0><<<grid, 256, SM_TOTAL>>>(h_p, W_hh, gh_p, TD,
                                              nullptr, nullptr);
        gru_step<<<NN, DD>>>(b_ih, b_hh, W_out, b_out, out, s);
    }
}

// round 11
// speedup vs baseline: 1.3740x; 1.1363x over previous
#include <cuda_runtime.h>
#include <cuda_bf16.h>
#include <math.h>
#include <cstdint>

// Problem constants
#define BB 256
#define TT 16
#define SS 20
#define DD 256
#define NN (BB*TT)          // 4096
#define TD (3*DD)           // 768
#define NC 1536             // 2*TD columns of precompute GEMM

// ---------------- device scratch ----------------
__device__ float g_G[(size_t)SS * NN * NC];// [s][n][1536]  (503 MB)
__device__ float g_h[NN * DD];             // hidden state
__device__ float g_m[NN];                  // soft readout multiplier
__device__ float g_gh[NN * TD];            // per-step h @ W_hh^T

// ---------------- helpers ----------------
__device__ __forceinline__ uint32_t smem_u32(const void* p) {
    uint32_t a;
    asm("{ .reg .u64 t; cvta.to.shared.u64 t, %1; cvt.u32.u64 %0, t; }"
        : "=r"(a) : "l"(p));
    return a;
}
__device__ __forceinline__ void cp16(uint32_t dst, const void* src) {
    asm volatile("cp.async.cg.shared.global [%0], [%1], 16;"
                 :: "r"(dst), "l"(src) : "memory");
}
__device__ __forceinline__ void cp_commit() {
    asm volatile("cp.async.commit_group;" ::: "memory");
}
template<int N>
__device__ __forceinline__ void cp_wait() {
    asm volatile("cp.async.wait_group %0;" :: "n"(N) : "memory");
}

// split a float2 (two consecutive k-elements) into bf16x2 hi + bf16x2 lo packs.
// pack layout: low 16 bits = first element (even k), high 16 = second (odd k).
__device__ __forceinline__ void split2(float2 v, uint32_t& hi, uint32_t& lo) {
    __nv_bfloat16 hx = __float2bfloat16_rn(v.x);
    __nv_bfloat16 hy = __float2bfloat16_rn(v.y);
    float rx = v.x - __bfloat162float(hx);
    float ry = v.y - __bfloat162float(hy);
    __nv_bfloat162 h2 = __halves2bfloat162(hx, hy);
    __nv_bfloat162 l2 = __halves2bfloat162(__float2bfloat16_rn(rx),
                                           __float2bfloat16_rn(ry));
    hi = *reinterpret_cast<uint32_t*>(&h2);
    lo = *reinterpret_cast<uint32_t*>(&l2);
}

__device__ __forceinline__ void mma_bf16(float c[4],
                                         uint32_t a0, uint32_t a1, uint32_t a2, uint32_t a3,
                                         uint32_t b0, uint32_t b1) {
    asm volatile(
        "mma.sync.aligned.m16n8k16.row.col.f32.bf16.bf16.f32 "
        "{%0,%1,%2,%3}, {%4,%5,%6,%7}, {%8,%9}, {%0,%1,%2,%3};"
        : "+f"(c[0]), "+f"(c[1]), "+f"(c[2]), "+f"(c[3])
        : "r"(a0), "r"(a1), "r"(a2), "r"(a3), "r"(b0), "r"(b1));
}

// ---------------- smem layout (dynamic, bytes) ----------------
#define SM_RPA   0
#define SM_RPB   1024
#define SM_TILES 2048
#define TILE_STRIDE 36              // floats per row (bank-conflict pad)
#define TILE_BYTES  (128*TILE_STRIDE*4)   // 18432
#define STAGE_BYTES (2*TILE_BYTES)        // 36864
#define SM_TOTAL (SM_TILES + 2*STAGE_BYTES)  // 75776

// ===== split-bf16 (3-term) mma.sync GEMM: C = A[Mtot x 256] @ Brows^T =====
// CTA tile 128(M) x 128(N), K=256 in 8 chunks of 32, cp.async double buffered.
// 8 warps: warpM = wid&1 (tile 64), warpN = wid>>1 (tile 32). m16n8k16 frags:
//   a0=(g,{2tg,2tg+1}) a1=(g+8,..) a2=(g,{2tg+8,2tg+9}) a3=(g+8,..)
//   b0=(n=g,k={2tg,2tg+1}) b1=(n=g,k={2tg+8,2tg+9})   (B stored [n][k])
//   c0,c1=(g, 2tg,2tg+1)  c2,c3=(g+8, 2tg,2tg+1)
// AMODE 1: A row r -> item_table[item_idxs[n*20+s]], r = s*4096+n.
// BMODE 1: B row j -> merged W_ih: row (j<768 ? j : j-768), +256 col if j>=768.
template<int AMODE, int BMODE>
__global__ __launch_bounds__(256)
void gemm_tc(const float* __restrict__ Aplain,
             const float* __restrict__ Bsrc,
             float* __restrict__ C,
             int Ncols,
             const int* __restrict__ item_idxs,
             const float* __restrict__ item_table) {
    extern __shared__ char smem[];
    const uint32_t smem_base = smem_u32(smem);
    const int tid  = threadIdx.x;
    const int wid  = tid >> 5;
    const int lane = tid & 31;
    const int bx = blockIdx.x, by = blockIdx.y;

    const float** rpA = (const float**)(smem + SM_RPA);
    const float** rpB = (const float**)(smem + SM_RPB);

    if (tid < 128) {
        int r = by * 128 + tid;
        const float* p;
        if (AMODE == 1) {
            int s = r >> 12, n = r & 4095;
            p = item_table + (size_t)item_idxs[n * SS + s] * DD;
        } else {
            p = Aplain + (size_t)r * DD;
        }
        rpA[tid] = p;
    } else {
        int j = bx * 128 + (tid - 128);
        const float* q;
        if (BMODE == 1) {
            int jj = (j >= TD) ? (j - TD) : j;       // true mod-768
            q = Bsrc + (size_t)jj * (2 * DD) + (j >= TD ? DD : 0);
        } else {
            q = Bsrc + (size_t)j * DD;
        }
        rpB[tid - 128] = q;
    }
    __syncthreads();

    // per-thread copy role: 2 threads per row, 16 floats each
    const int crow  = tid & 127;
    const int chalf = tid >> 7;                // 0 or 1 (k-half of 32)
    const float* aSrcBase = rpA[crow] + chalf * 16;
    const float* bSrcBase = rpB[crow] + chalf * 16;
    const uint32_t aDstBase = smem_base + SM_TILES + (uint32_t)crow * (TILE_STRIDE*4) + chalf * 64;
    const uint32_t bDstBase = aDstBase + TILE_BYTES;

    auto prefetch = [&](int kc, int buf) {
        uint32_t so = (uint32_t)buf * STAGE_BYTES;
        const float* as = aSrcBase + kc * 32;
        const float* bs = bSrcBase + kc * 32;
#pragma unroll
        for (int q = 0; q < 4; q++) {
            cp16(aDstBase + so + q * 16, as + q * 4);
            cp16(bDstBase + so + q * 16, bs + q * 4);
        }
    };

    const int warpM = wid & 1;
    const int warpN = wid >> 1;
    const int g  = lane >> 2;
    const int tg = lane & 3;
    const int mb = warpM * 64;
    const int nb = warpN * 32;

    float c[4][4][4];
#pragma unroll
    for (int mt = 0; mt < 4; mt++)
#pragma unroll
        for (int nt = 0; nt < 4; nt++)
#pragma unroll
            for (int e = 0; e < 4; e++) c[mt][nt][e] = 0.0f;

    prefetch(0, 0);
    cp_commit();

    for (int kc = 0; kc < 8; kc++) {
        if (kc < 7) {
            prefetch(kc + 1, (kc + 1) & 1);
            cp_commit();
            cp_wait<1>();
        } else {
            cp_wait<0>();
        }
        __syncthreads();

        const float* As = (const float*)(smem + SM_TILES + (kc & 1) * STAGE_BYTES);
        const float* Bs = As + 128 * TILE_STRIDE;

#pragma unroll
        for (int ks = 0; ks < 2; ks++) {
            const int k0 = ks * 16;
            // B fragments: b0 = k {2tg,2tg+1}, b1 = k {2tg+8,2tg+9}, col n=g
            uint32_t bh[4][2], bl[4][2];
#pragma unroll
            for (int nt = 0; nt < 4; nt++) {
                const float* br = Bs + (nb + nt * 8 + g) * TILE_STRIDE + k0 + 2 * tg;
                split2(*(const float2*)br,       bh[nt][0], bl[nt][0]);
                split2(*(const float2*)(br + 8), bh[nt][1], bl[nt][1]);
            }
#pragma unroll
            for (int mt = 0; mt < 4; mt++) {
                const float* ar0 = As + (mb + mt * 16 + g) * TILE_STRIDE + k0 + 2 * tg;
                const float* ar1 = ar0 + 8 * TILE_STRIDE;
                uint32_t ah0, ah1, ah2, ah3, al0, al1, al2, al3;
                split2(*(const float2*)ar0,       ah0, al0);  // (g,   k 2tg..)
                split2(*(const float2*)ar1,       ah1, al1);  // (g+8, k 2tg..)
                split2(*(const float2*)(ar0 + 8), ah2, al2);  // (g,   k 2tg+8..)
                split2(*(const float2*)(ar1 + 8), ah3, al3);  // (g+8, k 2tg+8..)
#pragma unroll
                for (int nt = 0; nt < 4; nt++) {
                    mma_bf16(c[mt][nt], al0, al1, al2, al3, bh[nt][0], bh[nt][1]);
                    mma_bf16(c[mt][nt], ah0, ah1, ah2, ah3, bl[nt][0], bl[nt][1]);
                    mma_bf16(c[mt][nt], ah0, ah1, ah2, ah3, bh[nt][0], bh[nt][1]);
                }
            }
        }
        __syncthreads();
    }

    // epilogue
#pragma unroll
    for (int mt = 0; mt < 4; mt++) {
        int row0 = by * 128 + mb + mt * 16 + g;
        int row1 = row0 + 8;
        float* c0p = C + (size_t)row0 * Ncols + bx * 128 + nb;
        float* c1p = C + (size_t)row1 * Ncols + bx * 128 + nb;
#pragma unroll
        for (int nt = 0; nt < 4; nt++) {
            int col = nt * 8 + tg * 2;
            *(float2*)(c0p + col) = make_float2(c[mt][nt][0], c[mt][nt][1]);
            *(float2*)(c1p + col) = make_float2(c[mt][nt][2], c[mt][nt][3]);
        }
    }
}

// ---------------- init h, m ----------------
__global__ void init_hm(const int* __restrict__ user_idxs,
                        const float* __restrict__ user_table) {
    int n = blockIdx.x;
    int d = threadIdx.x;
    g_h[n * DD + d] = user_table[(size_t)user_idxs[n] * DD + d];
    if (d == 0) g_m[n] = 1.0f;
}

// ---------------- fused GRU gate math + y reduction + state update ----------
__device__ __forceinline__ float sigmoidf_(float x) {
    return 1.0f / (1.0f + expf(-x));
}

__global__ __launch_bounds__(256)
void gru_step(const float* __restrict__ b_ih,
              const float* __restrict__ b_hh,
              const float* __restrict__ W_out,
              const float* __restrict__ b_out,
              float* __restrict__ out,
              int s) {
    const int n = blockIdx.x;
    const int d = threadIdx.x;

    const float* Grow  = g_G + ((size_t)s * NN + n) * NC;
    const float* ghrow = g_gh + (size_t)n * TD;

    float mm = g_m[n];
    float hv = g_h[n * DD + d];

    float gir = Grow[d]        + mm * Grow[TD + d]        + b_ih[d];
    float giz = Grow[DD + d]   + mm * Grow[TD + DD + d]   + b_ih[DD + d];
    float gin = Grow[2*DD + d] + mm * Grow[TD + 2*DD + d] + b_ih[2*DD + d];

    float ghr = ghrow[d]        + b_hh[d];
    float ghz = ghrow[DD + d]   + b_hh[DD + d];
    float ghn = ghrow[2*DD + d] + b_hh[2*DD + d];

    float r  = sigmoidf_(gir + ghr);
    float z  = sigmoidf_(giz + ghz);
    float nn = tanhf(gin + r * ghn);
    float hn = (1.0f - z) * nn + z * hv;

    g_h[n * DD + d] = hn;

    float part = hn * W_out[d];
#pragma unroll
    for (int off = 16; off > 0; off >>= 1)
        part += __shfl_down_sync(0xFFFFFFFFu, part, off);

    __shared__ float warpsum[8];
    if ((d & 31) == 0) warpsum[d >> 5] = part;
    __syncthreads();
    if (d == 0) {
        float y = b_out[0];
#pragma unroll
        for (int w = 0; w < 8; w++) y += warpsum[w];
        out[n * SS + s] = y;
        g_m[n] = sigmoidf_(y);
    }
}

// ---------------- launch ----------------
extern "C" void kernel_launch(void* const* d_in, const int* in_sizes, int n_in,
                              void* d_out, int out_size) {
    const int*   item_idxs  = (const int*)  d_in[0];
    const int*   user_idxs  = (const int*)  d_in[1];
    const float* item_table = (const float*)d_in[3];
    const float* user_table = (const float*)d_in[4];
    const float* W_ih       = (const float*)d_in[5];
    const float* W_hh       = (const float*)d_in[6];
    const float* b_ih       = (const float*)d_in[7];
    const float* b_hh       = (const float*)d_in[8];
    const float* W_out      = (const float*)d_in[9];
    const float* b_out      = (const float*)d_in[10];
    float* out = (float*)d_out;

    float *G_p, *h_p, *gh_p;
    cudaGetSymbolAddress((void**)&G_p,  g_G);
    cudaGetSymbolAddress((void**)&h_p,  g_h);
    cudaGetSymbolAddress((void**)&gh_p, g_gh);

    cudaFuncSetAttribute(gemm_tc<1,1>, cudaFuncAttributeMaxDynamicSharedMemorySize, SM_TOTAL);
    cudaFuncSetAttribute(gemm_tc<0,0>, cudaFuncAttributeMaxDynamicSharedMemorySize, SM_TOTAL);

    // init h, m
    init_hm<<<NN, DD>>>(user_idxs, user_table);

    // precompute G = gather(E) @ [W1 | W2]^T   (M=81920, Ncols=1536, K=256)
    {
        dim3 grid(NC / 128, (SS * NN) / 128);   // 12 x 640
        gemm_tc<1,1><<<grid, 256, SM_TOTAL>>>(nullptr, W_ih, G_p, NC,
                                              item_idxs, item_table);
    }

    // 20 sequential GRU steps
    for (int s = 0; s < SS; s++) {
        dim3 grid(TD / 128, NN / 128);          // 6 x 32
        gemm_tc<0,0><<<grid, 256, SM_TOTAL>>>(h_p, W_hh, gh_p, TD,
                                              nullptr, nullptr);
        gru_step<<<NN, DD>>>(b_ih, b_hh, W_out, b_out, out, s);
    }
}

// round 12
// speedup vs baseline: 1.7524x; 1.2754x over previous
#include <cuda_runtime.h>
#include <cuda_bf16.h>
#include <math.h>
#include <cstdint>

// Problem constants
#define BB 256
#define TT 16
#define SS 20
#define DD 256
#define NN (BB*TT)          // 4096
#define TD (3*DD)           // 768
#define NC 1536             // 2*TD columns of precompute GEMM
#define NITEMS 100000

// ---------------- device scratch ----------------
__device__ float g_G[(size_t)SS * NN * NC];   // [s][n][1536]  (503 MB)
__device__ float g_h[NN * DD];                // hidden state (f32)
__device__ float g_m[NN];                     // soft readout multiplier
__device__ float g_gh[NN * TD];               // per-step h @ W_hh^T

// packed bf16 (two consecutive k per u32; low 16 = even k)
__device__ uint32_t g_iT_hi[(size_t)NITEMS * 128];   // item_table hi  (51.2 MB)
__device__ uint32_t g_iT_lo[(size_t)NITEMS * 128];   // item_table lo
__device__ uint32_t g_Wih_hi[NC * 128];              // merged W_ih hi (0.79 MB)
__device__ uint32_t g_Wih_lo[NC * 128];
__device__ uint32_t g_Whh_hi[TD * 128];
__device__ uint32_t g_Whh_lo[TD * 128];
__device__ uint32_t g_h_hi[NN * 128];                // packed h
__device__ uint32_t g_h_lo[NN * 128];

// ---------------- helpers ----------------
__device__ __forceinline__ uint32_t smem_u32(const void* p) {
    uint32_t a;
    asm("{ .reg .u64 t; cvta.to.shared.u64 t, %1; cvt.u32.u64 %0, t; }"
        : "=r"(a) : "l"(p));
    return a;
}
__device__ __forceinline__ void cp16(uint32_t dst, const void* src) {
    asm volatile("cp.async.cg.shared.global [%0], [%1], 16;"
                 :: "r"(dst), "l"(src) : "memory");
}
__device__ __forceinline__ void cp_commit() {
    asm volatile("cp.async.commit_group;" ::: "memory");
}
template<int N>
__device__ __forceinline__ void cp_wait() {
    asm volatile("cp.async.wait_group %0;" :: "n"(N) : "memory");
}

// split two consecutive floats into bf16x2 hi + bf16x2 lo packs
__device__ __forceinline__ void split2(float2 v, uint32_t& hi, uint32_t& lo) {
    __nv_bfloat16 hx = __float2bfloat16_rn(v.x);
    __nv_bfloat16 hy = __float2bfloat16_rn(v.y);
    float rx = v.x - __bfloat162float(hx);
    float ry = v.y - __bfloat162float(hy);
    __nv_bfloat162 h2 = __halves2bfloat162(hx, hy);
    __nv_bfloat162 l2 = __halves2bfloat162(__float2bfloat16_rn(rx),
                                           __float2bfloat16_rn(ry));
    hi = *reinterpret_cast<uint32_t*>(&h2);
    lo = *reinterpret_cast<uint32_t*>(&l2);
}

__device__ __forceinline__ void mma_bf16(float c[4],
                                         uint32_t a0, uint32_t a1, uint32_t a2, uint32_t a3,
                                         uint32_t b0, uint32_t b1) {
    asm volatile(
        "mma.sync.aligned.m16n8k16.row.col.f32.bf16.bf16.f32 "
        "{%0,%1,%2,%3}, {%4,%5,%6,%7}, {%8,%9}, {%0,%1,%2,%3};"
        : "+f"(c[0]), "+f"(c[1]), "+f"(c[2]), "+f"(c[3])
        : "r"(a0), "r"(a1), "r"(a2), "r"(a3), "r"(b0), "r"(b1));
}

// ---------------- conversion prep kernels ----------------
__global__ void conv_item(const float* __restrict__ item_table) {
    size_t p = (size_t)blockIdx.x * blockDim.x + threadIdx.x;  // pair index
    if (p >= (size_t)NITEMS * 128) return;
    float2 v = *(const float2*)(item_table + 2 * p);
    split2(v, g_iT_hi[p], g_iT_lo[p]);
}
// merged W_ih: out row j (0..1535) -> src row (j<768?j:j-768), col +256 if j>=768
__global__ void conv_wih(const float* __restrict__ W_ih) {
    int j = blockIdx.x;       // 0..1535
    int p = threadIdx.x;      // 0..127 (k-pair)
    int jj = (j >= TD) ? (j - TD) : j;
    const float* src = W_ih + (size_t)jj * (2 * DD) + (j >= TD ? DD : 0) + 2 * p;
    split2(make_float2(src[0], src[1]), g_Wih_hi[j * 128 + p], g_Wih_lo[j * 128 + p]);
}
__global__ void conv_whh(const float* __restrict__ W_hh) {
    int j = blockIdx.x;       // 0..767
    int p = threadIdx.x;      // 0..127
    const float* src = W_hh + (size_t)j * DD + 2 * p;
    split2(make_float2(src[0], src[1]), g_Whh_hi[j * 128 + p], g_Whh_lo[j * 128 + p]);
}

// ---------------- smem layout (dynamic) ----------------
#define PSTR 20                                // u32 stride per row (conflict-free)
#define T_U32 (128 * PSTR)                     // 2560 u32 per tile
#define TILE_B (T_U32 * 4)                     // 10240 bytes
#define STAGE_B (4 * TILE_B)                   // Ahi,Alo,Bhi,Blo = 40960
#define SM_OFFA 0
#define SM_OFFB 512
#define SM_TILES 1024
#define SM_TOTAL (SM_TILES + 2 * STAGE_B)      // 82944

// ===== pre-split bf16 (3-term) GEMM: C = A[Mtot x 256] @ Brows^T =====
// CTA tile 128(M) x 128(N), K=256 in 8 chunks of 32, cp.async double buffered.
// Operands pre-packed u32 (two bf16/k-pair). Row stride 128 u32.
// AMODE 1: A row r -> item row item_idxs[n*20+s], r = s*4096+n. Else row r.
template<int AMODE>
__global__ __launch_bounds__(256)
void gemm_tc(const uint32_t* __restrict__ Ahi, const uint32_t* __restrict__ Alo,
             const uint32_t* __restrict__ Bhi, const uint32_t* __restrict__ Blo,
             float* __restrict__ C, int Ncols,
             const int* __restrict__ item_idxs) {
    extern __shared__ char smem[];
    const uint32_t smem_base = smem_u32(smem);
    const int tid  = threadIdx.x;
    const int wid  = tid >> 5;
    const int lane = tid & 31;
    const int bx = blockIdx.x, by = blockIdx.y;

    uint32_t* offA = (uint32_t*)(smem + SM_OFFA);
    uint32_t* offB = (uint32_t*)(smem + SM_OFFB);

    if (tid < 128) {
        int r = by * 128 + tid;
        uint32_t off;
        if (AMODE == 1) {
            int s = r >> 12, n = r & 4095;
            off = (uint32_t)item_idxs[n * SS + s] * 128u;
        } else {
            off = (uint32_t)r * 128u;
        }
        offA[tid] = off;
    } else {
        int j = bx * 128 + (tid - 128);
        offB[tid - 128] = (uint32_t)j * 128u;
    }
    __syncthreads();

    // copy roles: 2 threads per row, each moves 8 u32 (32B = 2x cp16) per tile
    const int crow  = tid & 127;
    const int chalf = tid >> 7;                 // 0/1: which 8-u32 half of the 16
    const uint32_t aOff = offA[crow] + chalf * 8;
    const uint32_t bOff = offB[crow] + chalf * 8;
    const uint32_t dstRow = smem_base + SM_TILES
                          + (uint32_t)(crow * PSTR + chalf * 8) * 4u;

    auto prefetch = [&](int kc, int buf) {
        uint32_t so = (uint32_t)buf * STAGE_B;
        uint32_t ko = (uint32_t)kc * 16;        // u32 per chunk of K=32
        const uint32_t* s0 = Ahi + aOff + ko;
        const uint32_t* s1 = Alo + aOff + ko;
        const uint32_t* s2 = Bhi + bOff + ko;
        const uint32_t* s3 = Blo + bOff + ko;
        cp16(dstRow + so + 0 * TILE_B,      s0);
        cp16(dstRow + so + 0 * TILE_B + 16, s0 + 4);
        cp16(dstRow + so + 1 * TILE_B,      s1);
        cp16(dstRow + so + 1 * TILE_B + 16, s1 + 4);
        cp16(dstRow + so + 2 * TILE_B,      s2);
        cp16(dstRow + so + 2 * TILE_B + 16, s2 + 4);
        cp16(dstRow + so + 3 * TILE_B,      s3);
        cp16(dstRow + so + 3 * TILE_B + 16, s3 + 4);
    };

    const int warpM = wid & 1;
    const int warpN = wid >> 1;
    const int g  = lane >> 2;
    const int tg = lane & 3;
    const int mb = warpM * 64;
    const int nb = warpN * 32;

    float c[4][4][4];
#pragma unroll
    for (int mt = 0; mt < 4; mt++)
#pragma unroll
        for (int nt = 0; nt < 4; nt++)
#pragma unroll
            for (int e = 0; e < 4; e++) c[mt][nt][e] = 0.0f;

    prefetch(0, 0);
    cp_commit();

    for (int kc = 0; kc < 8; kc++) {
        if (kc < 7) {
            prefetch(kc + 1, (kc + 1) & 1);
            cp_commit();
            cp_wait<1>();
        } else {
            cp_wait<0>();
        }
        __syncthreads();

        const uint32_t* AhiS = (const uint32_t*)(smem + SM_TILES + (kc & 1) * STAGE_B);
        const uint32_t* AloS = AhiS + T_U32;
        const uint32_t* BhiS = AloS + T_U32;
        const uint32_t* BloS = BhiS + T_U32;

#pragma unroll
        for (int ks = 0; ks < 2; ks++) {
            const int kp = ks * 8 + tg;         // u32 (k-pair) index
            uint32_t bh[4][2], bl[4][2];
#pragma unroll
            for (int nt = 0; nt < 4; nt++) {
                int bp = (nb + nt * 8 + g) * PSTR + kp;
                bh[nt][0] = BhiS[bp];  bh[nt][1] = BhiS[bp + 4];
                bl[nt][0] = BloS[bp];  bl[nt][1] = BloS[bp + 4];
            }
#pragma unroll
            for (int mt = 0; mt < 4; mt++) {
                int ap0 = (mb + mt * 16 + g) * PSTR + kp;
                int ap1 = ap0 + 8 * PSTR;
                uint32_t ah0 = AhiS[ap0], ah1 = AhiS[ap1];
                uint32_t ah2 = AhiS[ap0 + 4], ah3 = AhiS[ap1 + 4];
                uint32_t al0 = AloS[ap0], al1 = AloS[ap1];
                uint32_t al2 = AloS[ap0 + 4], al3 = AloS[ap1 + 4];
#pragma unroll
                for (int nt = 0; nt < 4; nt++) {
                    mma_bf16(c[mt][nt], al0, al1, al2, al3, bh[nt][0], bh[nt][1]);
                    mma_bf16(c[mt][nt], ah0, ah1, ah2, ah3, bl[nt][0], bl[nt][1]);
                    mma_bf16(c[mt][nt], ah0, ah1, ah2, ah3, bh[nt][0], bh[nt][1]);
                }
            }
        }
        __syncthreads();
    }

    // epilogue
#pragma unroll
    for (int mt = 0; mt < 4; mt++) {
        int row0 = by * 128 + mb + mt * 16 + g;
        int row1 = row0 + 8;
        float* c0p = C + (size_t)row0 * Ncols + bx * 128 + nb;
        float* c1p = C + (size_t)row1 * Ncols + bx * 128 + nb;
#pragma unroll
        for (int nt = 0; nt < 4; nt++) {
            int col = nt * 8 + tg * 2;
            *(float2*)(c0p + col) = make_float2(c[mt][nt][0], c[mt][nt][1]);
            *(float2*)(c1p + col) = make_float2(c[mt][nt][2], c[mt][nt][3]);
        }
    }
}

// ---------------- init h, m (f32 + packed) ----------------
__global__ void init_hm(const int* __restrict__ user_idxs,
                        const float* __restrict__ user_table) {
    int n = blockIdx.x;
    int d = threadIdx.x;
    float hv = user_table[(size_t)user_idxs[n] * DD + d];
    g_h[n * DD + d] = hv;
    // pack pairs
    float hnb = __shfl_down_sync(0xFFFFFFFFu, hv, 1);
    if ((d & 1) == 0) {
        uint32_t hi, lo;
        split2(make_float2(hv, hnb), hi, lo);
        g_h_hi[n * 128 + (d >> 1)] = hi;
        g_h_lo[n * 128 + (d >> 1)] = lo;
    }
    if (d == 0) g_m[n] = 1.0f;
}

// ---------------- fused GRU gate math + y + state update ----------
__device__ __forceinline__ float sigmoidf_(float x) {
    return 1.0f / (1.0f + expf(-x));
}

__global__ __launch_bounds__(256)
void gru_step(const float* __restrict__ b_ih,
              const float* __restrict__ b_hh,
              const float* __restrict__ W_out,
              const float* __restrict__ b_out,
              float* __restrict__ out,
              int s) {
    const int n = blockIdx.x;
    const int d = threadIdx.x;

    const float* Grow  = g_G + ((size_t)s * NN + n) * NC;
    const float* ghrow = g_gh + (size_t)n * TD;

    float mm = g_m[n];
    float hv = g_h[n * DD + d];

    float gir = Grow[d]        + mm * Grow[TD + d]        + b_ih[d];
    float giz = Grow[DD + d]   + mm * Grow[TD + DD + d]   + b_ih[DD + d];
    float gin = Grow[2*DD + d] + mm * Grow[TD + 2*DD + d] + b_ih[2*DD + d];

    float ghr = ghrow[d]        + b_hh[d];
    float ghz = ghrow[DD + d]   + b_hh[DD + d];
    float ghn = ghrow[2*DD + d] + b_hh[2*DD + d];

    float r  = sigmoidf_(gir + ghr);
    float z  = sigmoidf_(giz + ghz);
    float nn = tanhf(gin + r * ghn);
    float hn = (1.0f - z) * nn + z * hv;

    g_h[n * DD + d] = hn;
    // pack pairs for next-step GEMM
    float hnb = __shfl_down_sync(0xFFFFFFFFu, hn, 1);
    if ((d & 1) == 0) {
        uint32_t hi, lo;
        split2(make_float2(hn, hnb), hi, lo);
        g_h_hi[n * 128 + (d >> 1)] = hi;
        g_h_lo[n * 128 + (d >> 1)] = lo;
    }

    float part = hn * W_out[d];
#pragma unroll
    for (int off = 16; off > 0; off >>= 1)
        part += __shfl_down_sync(0xFFFFFFFFu, part, off);

    __shared__ float warpsum[8];
    if ((d & 31) == 0) warpsum[d >> 5] = part;
    __syncthreads();
    if (d == 0) {
        float y = b_out[0];
#pragma unroll
        for (int w = 0; w < 8; w++) y += warpsum[w];
        out[n * SS + s] = y;
        g_m[n] = sigmoidf_(y);
    }
}

// ---------------- launch ----------------
extern "C" void kernel_launch(void* const* d_in, const int* in_sizes, int n_in,
                              void* d_out, int out_size) {
    const int*   item_idxs  = (const int*)  d_in[0];
    const int*   user_idxs  = (const int*)  d_in[1];
    const float* item_table = (const float*)d_in[3];
    const float* user_table = (const float*)d_in[4];
    const float* W_ih       = (const float*)d_in[5];
    const float* W_hh       = (const float*)d_in[6];
    const float* b_ih       = (const float*)d_in[7];
    const float* b_hh       = (const float*)d_in[8];
    const float* W_out      = (const float*)d_in[9];
    const float* b_out      = (const float*)d_in[10];
    float* out = (float*)d_out;

    float *G_p, *gh_p;
    uint32_t *iTh, *iTl, *Wih_h, *Wih_l, *Whh_h, *Whh_l, *hh, *hl;
    cudaGetSymbolAddress((void**)&G_p,  g_G);
    cudaGetSymbolAddress((void**)&gh_p, g_gh);
    cudaGetSymbolAddress((void**)&iTh,  g_iT_hi);
    cudaGetSymbolAddress((void**)&iTl,  g_iT_lo);
    cudaGetSymbolAddress((void**)&Wih_h, g_Wih_hi);
    cudaGetSymbolAddress((void**)&Wih_l, g_Wih_lo);
    cudaGetSymbolAddress((void**)&Whh_h, g_Whh_hi);
    cudaGetSymbolAddress((void**)&Whh_l, g_Whh_lo);
    cudaGetSymbolAddress((void**)&hh,   g_h_hi);
    cudaGetSymbolAddress((void**)&hl,   g_h_lo);

    cudaFuncSetAttribute(gemm_tc<1>, cudaFuncAttributeMaxDynamicSharedMemorySize, SM_TOTAL);
    cudaFuncSetAttribute(gemm_tc<0>, cudaFuncAttributeMaxDynamicSharedMemorySize, SM_TOTAL);

    // one-time conversions
    conv_item<<<(NITEMS * 128 + 255) / 256, 256>>>(item_table);
    conv_wih<<<NC, 128>>>(W_ih);
    conv_whh<<<TD, 128>>>(W_hh);
    init_hm<<<NN, DD>>>(user_idxs, user_table);

    // precompute G = gather(E) @ [W1 | W2]^T   (M=81920, Ncols=1536, K=256)
    {
        dim3 grid(NC / 128, (SS * NN) / 128);   // 12 x 640
        gemm_tc<1><<<grid, 256, SM_TOTAL>>>(iTh, iTl, Wih_h, Wih_l,
                                            G_p, NC, item_idxs);
    }

    // 20 sequential GRU steps
    for (int s = 0; s < SS; s++) {
        dim3 grid(TD / 128, NN / 128);          // 6 x 32
        gemm_tc<0><<<grid, 256, SM_TOTAL>>>(hh, hl, Whh_h, Whh_l,
                                            gh_p, TD, nullptr);
        gru_step<<<NN, DD>>>(b_ih, b_hh, W_out, b_out, out, s);
    }
}

// round 13
// speedup vs baseline: 2.5338x; 1.4459x over previous
#include <cuda_runtime.h>
#include <cuda_bf16.h>
#include <math.h>
#include <cstdint>

// Problem constants
#define BB 256
#define TT 16
#define SS 20
#define DD 256
#define NN (BB*TT)          // 4096
#define TD (3*DD)           // 768
#define NC 1536             // 2*TD columns of precompute GEMM
#define NITEMS 100000

// ---------------- device scratch ----------------
__device__ float g_G[(size_t)SS * NN * NC];   // [s][n][1536]  (503 MB)
__device__ float g_h[NN * DD];                // hidden state (f32)
__device__ float g_m[NN];                     // soft readout multiplier
__device__ float g_gh[NN * TD];               // per-step h @ W_hh^T

// packed bf16 (two consecutive k per u32; low 16 = even k)
__device__ uint32_t g_iT_hi[(size_t)NITEMS * 128];
__device__ uint32_t g_iT_lo[(size_t)NITEMS * 128];
__device__ uint32_t g_Wih_hi[NC * 128];
__device__ uint32_t g_Wih_lo[NC * 128];
__device__ uint32_t g_Whh_hi[TD * 128];
__device__ uint32_t g_Whh_lo[TD * 128];
__device__ uint32_t g_h_hi[NN * 128];
__device__ uint32_t g_h_lo[NN * 128];

// ---------------- helpers ----------------
__device__ __forceinline__ uint32_t smem_u32(const void* p) {
    uint32_t a;
    asm("{ .reg .u64 t; cvta.to.shared.u64 t, %1; cvt.u32.u64 %0, t; }"
        : "=r"(a) : "l"(p));
    return a;
}
__device__ __forceinline__ void cp16(uint32_t dst, const void* src) {
    asm volatile("cp.async.cg.shared.global [%0], [%1], 16;"
                 :: "r"(dst), "l"(src) : "memory");
}
__device__ __forceinline__ void cp_commit() {
    asm volatile("cp.async.commit_group;" ::: "memory");
}
template<int N>
__device__ __forceinline__ void cp_wait() {
    asm volatile("cp.async.wait_group %0;" :: "n"(N) : "memory");
}
__device__ __forceinline__ void ldmx4(uint32_t& r0, uint32_t& r1,
                                      uint32_t& r2, uint32_t& r3, uint32_t addr) {
    asm volatile("ldmatrix.sync.aligned.m8n8.x4.shared.b16 {%0,%1,%2,%3}, [%4];"
                 : "=r"(r0), "=r"(r1), "=r"(r2), "=r"(r3) : "r"(addr));
}

// split two consecutive floats into bf16x2 hi + bf16x2 lo packs
__device__ __forceinline__ void split2(float2 v, uint32_t& hi, uint32_t& lo) {
    __nv_bfloat16 hx = __float2bfloat16_rn(v.x);
    __nv_bfloat16 hy = __float2bfloat16_rn(v.y);
    float rx = v.x - __bfloat162float(hx);
    float ry = v.y - __bfloat162float(hy);
    __nv_bfloat162 h2 = __halves2bfloat162(hx, hy);
    __nv_bfloat162 l2 = __halves2bfloat162(__float2bfloat16_rn(rx),
                                           __float2bfloat16_rn(ry));
    hi = *reinterpret_cast<uint32_t*>(&h2);
    lo = *reinterpret_cast<uint32_t*>(&l2);
}

__device__ __forceinline__ void mma_bf16(float c[4],
                                         uint32_t a0, uint32_t a1, uint32_t a2, uint32_t a3,
                                         uint32_t b0, uint32_t b1) {
    asm volatile(
        "mma.sync.aligned.m16n8k16.row.col.f32.bf16.bf16.f32 "
        "{%0,%1,%2,%3}, {%4,%5,%6,%7}, {%8,%9}, {%0,%1,%2,%3};"
        : "+f"(c[0]), "+f"(c[1]), "+f"(c[2]), "+f"(c[3])
        : "r"(a0), "r"(a1), "r"(a2), "r"(a3), "r"(b0), "r"(b1));
}

// ---------------- conversion prep kernels ----------------
__global__ void conv_item(const float* __restrict__ item_table) {
    size_t p = (size_t)blockIdx.x * blockDim.x + threadIdx.x;
    if (p >= (size_t)NITEMS * 128) return;
    float2 v = *(const float2*)(item_table + 2 * p);
    split2(v, g_iT_hi[p], g_iT_lo[p]);
}
__global__ void conv_wih(const float* __restrict__ W_ih) {
    int j = blockIdx.x;       // 0..1535
    int p = threadIdx.x;      // 0..127
    int jj = (j >= TD) ? (j - TD) : j;
    const float* src = W_ih + (size_t)jj * (2 * DD) + (j >= TD ? DD : 0) + 2 * p;
    split2(make_float2(src[0], src[1]), g_Wih_hi[j * 128 + p], g_Wih_lo[j * 128 + p]);
}
__global__ void conv_whh(const float* __restrict__ W_hh) {
    int j = blockIdx.x;       // 0..767
    int p = threadIdx.x;      // 0..127
    const float* src = W_hh + (size_t)j * DD + 2 * p;
    split2(make_float2(src[0], src[1]), g_Whh_hi[j * 128 + p], g_Whh_lo[j * 128 + p]);
}

// ---------------- GEMM ----------------
#define PSTR 20                                // u32 stride per smem row

// ===== pre-split bf16 (3-term) GEMM with ldmatrix fragment loads =====
// Tile: M = 32*MTN (MTN per-warp 16-row blocks x 2 warpM), N = 128.
// K=256 in 8 chunks of 32, cp.async double buffered.
// AMODE 1: A row r -> item row item_idxs[n*20+s], r = s*4096+n. Else row r.
template<int AMODE, int MTN>
__global__ __launch_bounds__(256)
void gemm_tc(const uint32_t* __restrict__ Ahi, const uint32_t* __restrict__ Alo,
             const uint32_t* __restrict__ Bhi, const uint32_t* __restrict__ Blo,
             float* __restrict__ C, int Ncols,
             const int* __restrict__ item_idxs) {
    constexpr int ROWSA   = 32 * MTN;
    constexpr int A_T_U32 = ROWSA * PSTR;
    constexpr int B_T_U32 = 128 * PSTR;
    constexpr int STAGE_U32 = 2 * A_T_U32 + 2 * B_T_U32;
    constexpr int STAGE_B   = STAGE_U32 * 4;

    extern __shared__ char smem[];
    const uint32_t smem_base = smem_u32(smem);
    const int tid  = threadIdx.x;
    const int wid  = tid >> 5;
    const int lane = tid & 31;
    const int bx = blockIdx.x, by = blockIdx.y;

    uint32_t* offA = (uint32_t*)(smem);          // ROWSA entries
    uint32_t* offB = (uint32_t*)(smem + 512);    // 128 entries

    if (tid < ROWSA) {
        int r = by * ROWSA + tid;
        uint32_t off;
        if (AMODE == 1) {
            int s = r >> 12, n = r & 4095;
            off = (uint32_t)item_idxs[n * SS + s] * 128u;
        } else {
            off = (uint32_t)r * 128u;
        }
        offA[tid] = off;
    } else if (tid >= 128) {
        int j = bx * 128 + (tid - 128);
        offB[tid - 128] = (uint32_t)j * 128u;
    }
    __syncthreads();

    // ---- async tile copy: 16B units, order [Ahi][Alo][Bhi][Blo] ----
    const uint32_t stage0 = smem_base + 1024;
    auto prefetch = [&](int kc, int buf) {
        const uint32_t sb = stage0 + (uint32_t)buf * STAGE_B;
        const uint32_t ko = (uint32_t)kc * 16;   // u32 per K=32 chunk
        constexpr int UA = ROWSA * 4;            // units per A tile
        constexpr int UB = 128 * 4;
        constexpr int TOT = 2 * UA + 2 * UB;
        for (int u = tid; u < TOT; u += 256) {
            const uint32_t* src;
            uint32_t dst;
            if (u < 2 * UA) {
                int t = u / UA;                  // 0=hi 1=lo
                int v = u - t * UA;
                int row = v >> 2, q = v & 3;
                src = (t ? Alo : Ahi) + offA[row] + ko + q * 4;
                dst = sb + (uint32_t)(t * A_T_U32 + row * PSTR + q * 4) * 4u;
            } else {
                int w = u - 2 * UA;
                int t = w / UB;
                int v = w - t * UB;
                int row = v >> 2, q = v & 3;
                src = (t ? Blo : Bhi) + offB[row] + ko + q * 4;
                dst = sb + (uint32_t)(2 * A_T_U32 + t * B_T_U32 + row * PSTR + q * 4) * 4u;
            }
            cp16(dst, src);
        }
    };

    const int warpM = wid & 1;
    const int warpN = wid >> 1;
    const int mb = warpM * (16 * MTN);
    const int nb = warpN * 32;
    const int sel = lane >> 3;
    const int rl  = lane & 7;

    // per-lane ldmatrix row byte-offsets (within a tile)
    int aRowOff[MTN], bRowOff[2];
#pragma unroll
    for (int mt = 0; mt < MTN; mt++)
        aRowOff[mt] = (mb + mt * 16 + (sel & 1) * 8 + rl) * (PSTR * 4) + (sel >> 1) * 16;
#pragma unroll
    for (int p = 0; p < 2; p++)
        bRowOff[p] = (nb + p * 16 + (sel >> 1) * 8 + rl) * (PSTR * 4) + (sel & 1) * 16;

    float c[MTN][4][4];
#pragma unroll
    for (int mt = 0; mt < MTN; mt++)
#pragma unroll
        for (int nt = 0; nt < 4; nt++)
#pragma unroll
            for (int e = 0; e < 4; e++) c[mt][nt][e] = 0.0f;

    prefetch(0, 0);
    cp_commit();

    for (int kc = 0; kc < 8; kc++) {
        if (kc < 7) {
            prefetch(kc + 1, (kc + 1) & 1);
            cp_commit();
            cp_wait<1>();
        } else {
            cp_wait<0>();
        }
        __syncthreads();

        const uint32_t sb   = stage0 + (uint32_t)(kc & 1) * STAGE_B;
        const uint32_t AhiB = sb;
        const uint32_t AloB = sb + A_T_U32 * 4;
        const uint32_t BhiB = sb + 2 * A_T_U32 * 4;
        const uint32_t BloB = BhiB + B_T_U32 * 4;

#pragma unroll
        for (int ks = 0; ks < 2; ks++) {
            const int kofs = ks * 32;
            uint32_t bh[4][2], bl[4][2];
#pragma unroll
            for (int p = 0; p < 2; p++) {
                ldmx4(bh[2*p][0], bh[2*p][1], bh[2*p+1][0], bh[2*p+1][1],
                      BhiB + bRowOff[p] + kofs);
                ldmx4(bl[2*p][0], bl[2*p][1], bl[2*p+1][0], bl[2*p+1][1],
                      BloB + bRowOff[p] + kofs);
            }
#pragma unroll
            for (int mt = 0; mt < MTN; mt++) {
                uint32_t ah0, ah1, ah2, ah3, al0, al1, al2, al3;
                ldmx4(ah0, ah1, ah2, ah3, AhiB + aRowOff[mt] + kofs);
                ldmx4(al0, al1, al2, al3, AloB + aRowOff[mt] + kofs);
#pragma unroll
                for (int nt = 0; nt < 4; nt++) {
                    mma_bf16(c[mt][nt], al0, al1, al2, al3, bh[nt][0], bh[nt][1]);
                    mma_bf16(c[mt][nt], ah0, ah1, ah2, ah3, bl[nt][0], bl[nt][1]);
                    mma_bf16(c[mt][nt], ah0, ah1, ah2, ah3, bh[nt][0], bh[nt][1]);
                }
            }
        }
        __syncthreads();
    }

    // epilogue: c0,c1 -> (row g, cols 2tg,2tg+1), c2,c3 -> (row g+8)
    const int g  = lane >> 2;
    const int tg = lane & 3;
#pragma unroll
    for (int mt = 0; mt < MTN; mt++) {
        int row0 = by * ROWSA + mb + mt * 16 + g;
        int row1 = row0 + 8;
        float* c0p = C + (size_t)row0 * Ncols + bx * 128 + nb;
        float* c1p = C + (size_t)row1 * Ncols + bx * 128 + nb;
#pragma unroll
        for (int nt = 0; nt < 4; nt++) {
            int col = nt * 8 + tg * 2;
            *(float2*)(c0p + col) = make_float2(c[mt][nt][0], c[mt][nt][1]);
            *(float2*)(c1p + col) = make_float2(c[mt][nt][2], c[mt][nt][3]);
        }
    }
}

// ---------------- init h, m (f32 + packed) ----------------
__global__ void init_hm(const int* __restrict__ user_idxs,
                        const float* __restrict__ user_table) {
    int n = blockIdx.x;
    int d = threadIdx.x;
    float hv = user_table[(size_t)user_idxs[n] * DD + d];
    g_h[n * DD + d] = hv;
    float hnb = __shfl_down_sync(0xFFFFFFFFu, hv, 1);
    if ((d & 1) == 0) {
        uint32_t hi, lo;
        split2(make_float2(hv, hnb), hi, lo);
        g_h_hi[n * 128 + (d >> 1)] = hi;
        g_h_lo[n * 128 + (d >> 1)] = lo;
    }
    if (d == 0) g_m[n] = 1.0f;
}

// ---------------- fused GRU gate math + y + state update ----------
__device__ __forceinline__ float sigmoidf_(float x) {
    return 1.0f / (1.0f + expf(-x));
}

__global__ __launch_bounds__(256)
void gru_step(const float* __restrict__ b_ih,
              const float* __restrict__ b_hh,
              const float* __restrict__ W_out,
              const float* __restrict__ b_out,
              float* __restrict__ out,
              int s) {
    const int n = blockIdx.x;
    const int d = threadIdx.x;

    const float* Grow  = g_G + ((size_t)s * NN + n) * NC;
    const float* ghrow = g_gh + (size_t)n * TD;

    float mm = g_m[n];
    float hv = g_h[n * DD + d];

    float gir = Grow[d]        + mm * Grow[TD + d]        + b_ih[d];
    float giz = Grow[DD + d]   + mm * Grow[TD + DD + d]   + b_ih[DD + d];
    float gin = Grow[2*DD + d] + mm * Grow[TD + 2*DD + d] + b_ih[2*DD + d];

    float ghr = ghrow[d]        + b_hh[d];
    float ghz = ghrow[DD + d]   + b_hh[DD + d];
    float ghn = ghrow[2*DD + d] + b_hh[2*DD + d];

    float r  = sigmoidf_(gir + ghr);
    float z  = sigmoidf_(giz + ghz);
    float nn = tanhf(gin + r * ghn);
    float hn = (1.0f - z) * nn + z * hv;

    g_h[n * DD + d] = hn;
    float hnb = __shfl_down_sync(0xFFFFFFFFu, hn, 1);
    if ((d & 1) == 0) {
        uint32_t hi, lo;
        split2(make_float2(hn, hnb), hi, lo);
        g_h_hi[n * 128 + (d >> 1)] = hi;
        g_h_lo[n * 128 + (d >> 1)] = lo;
    }

    float part = hn * W_out[d];
#pragma unroll
    for (int off = 16; off > 0; off >>= 1)
        part += __shfl_down_sync(0xFFFFFFFFu, part, off);

    __shared__ float warpsum[8];
    if ((d & 31) == 0) warpsum[d >> 5] = part;
    __syncthreads();
    if (d == 0) {
        float y = b_out[0];
#pragma unroll
        for (int w = 0; w < 8; w++) y += warpsum[w];
        out[n * SS + s] = y;
        g_m[n] = sigmoidf_(y);
    }
}

// ---------------- launch ----------------
extern "C" void kernel_launch(void* const* d_in, const int* in_sizes, int n_in,
                              void* d_out, int out_size) {
    const int*   item_idxs  = (const int*)  d_in[0];
    const int*   user_idxs  = (const int*)  d_in[1];
    const float* item_table = (const float*)d_in[3];
    const float* user_table = (const float*)d_in[4];
    const float* W_ih       = (const float*)d_in[5];
    const float* W_hh       = (const float*)d_in[6];
    const float* b_ih       = (const float*)d_in[7];
    const float* b_hh       = (const float*)d_in[8];
    const float* W_out      = (const float*)d_in[9];
    const float* b_out      = (const float*)d_in[10];
    float* out = (float*)d_out;

    float *G_p, *gh_p;
    uint32_t *iTh, *iTl, *Wih_h, *Wih_l, *Whh_h, *Whh_l, *hh, *hl;
    cudaGetSymbolAddress((void**)&G_p,  g_G);
    cudaGetSymbolAddress((void**)&gh_p, g_gh);
    cudaGetSymbolAddress((void**)&iTh,  g_iT_hi);
    cudaGetSymbolAddress((void**)&iTl,  g_iT_lo);
    cudaGetSymbolAddress((void**)&Wih_h, g_Wih_hi);
    cudaGetSymbolAddress((void**)&Wih_l, g_Wih_lo);
    cudaGetSymbolAddress((void**)&Whh_h, g_Whh_hi);
    cudaGetSymbolAddress((void**)&Whh_l, g_Whh_lo);
    cudaGetSymbolAddress((void**)&hh,   g_h_hi);
    cudaGetSymbolAddress((void**)&hl,   g_h_lo);

    // smem sizes: MTN=4: 1024 + 2*40960 = 82944 ; MTN=2: 1024 + 2*30720 = 62464
    cudaFuncSetAttribute(gemm_tc<1,4>, cudaFuncAttributeMaxDynamicSharedMemorySize, 82944);
    cudaFuncSetAttribute(gemm_tc<0,2>, cudaFuncAttributeMaxDynamicSharedMemorySize, 62464);

    // one-time conversions
    conv_item<<<(NITEMS * 128 + 255) / 256, 256>>>(item_table);
    conv_wih<<<NC, 128>>>(W_ih);
    conv_whh<<<TD, 128>>>(W_hh);
    init_hm<<<NN, DD>>>(user_idxs, user_table);

    // precompute G = gather(E) @ [W1 | W2]^T   (M=81920, Ncols=1536, K=256)
    {
        dim3 grid(NC / 128, (SS * NN) / 128);   // 12 x 640
        gemm_tc<1,4><<<grid, 256, 82944>>>(iTh, iTl, Wih_h, Wih_l,
                                           G_p, NC, item_idxs);
    }

    // 20 sequential GRU steps
    for (int s = 0; s < SS; s++) {
        dim3 grid(TD / 128, NN / 64);           // 6 x 64
        gemm_tc<0,2><<<grid, 256, 62464>>>(hh, hl, Whh_h, Whh_l,
                                           gh_p, TD, nullptr);
        gru_step<<<NN, DD>>>(b_ih, b_hh, W_out, b_out, out, s);
    }
}